// round 2
// baseline (speedup 1.0000x reference)
#include <cuda_runtime.h>
#include <math.h>

// ---------------- problem constants ----------------
#define BB    128        // batch
#define NI    8192       // items
#define NW    16384      // words
#define EE    64         // embedding
#define KP    4          // prototypes
#define TWOE  128

// output layout (floats, concatenated)
#define OUT_RATING  0
#define OUT_TEXT    (128*8192)                       // 1048576
#define OUT_CFMU    (OUT_TEXT + 128*16384)           // 3145728
#define OUT_CFLV    (OUT_CFMU + 4*128*64)            // 3178496
#define OUT_TXMU    (OUT_CFLV + 4*128*64)            // 3211264
#define OUT_TXLV    (OUT_TXMU + 4*128*64)            // 3244032

// ---------------- scratch (static device memory; no allocations) ----------------
__device__ float g_protos_cf[KP*EE];
__device__ float g_protos_tx[KP*EE];
__device__ float g_items_cf[NI*EE];
__device__ float g_items_tx[NW*EE];
__device__ float g_cates_cf[NI*KP];
__device__ float g_cates_tx[NW*KP];
__device__ float g_rnorm_cf[KP*BB];
__device__ float g_rnorm_tx[KP*BB];
__device__ float g_P1[NI*TWOE];
__device__ float g_P2[NI*TWOE];
__device__ float g_M [NI*TWOE];
__device__ float g_part_cf[16*512*TWOE];   // 16 chunks of 512 n's
__device__ float g_part_tx[32*512*TWOE];

// ---------------- k0: normalize prototype embeddings ----------------
__global__ void proto_norm_k(const float* __restrict__ cfp, const float* __restrict__ txp) {
    int tid = threadIdx.x;
    int w = tid >> 5, lane = tid & 31;
    const float* src = (w < 4) ? cfp : txp;
    float* dst = (w < 4) ? g_protos_cf : g_protos_tx;
    int row = w & 3;
    float v0 = src[row*EE + lane];
    float v1 = src[row*EE + 32 + lane];
    float s = v0*v0 + v1*v1;
    #pragma unroll
    for (int off = 16; off; off >>= 1) s += __shfl_xor_sync(0xffffffffu, s, off);
    float inv = 1.0f / fmaxf(sqrtf(s), 1e-12f);
    dst[row*EE + lane]      = v0 * inv;
    dst[row*EE + 32 + lane] = v1 * inv;
}

// ---------------- k1: normalize item embeddings + cates softmax ----------------
// one warp per item row; 8 rows per block
__global__ void __launch_bounds__(256) items_cates_k(
        const float* __restrict__ emb, const float* __restrict__ protos_g,
        float* __restrict__ items_out, float* __restrict__ cates_out, int N)
{
    __shared__ float ps[KP*EE];
    int tid = threadIdx.x;
    ps[tid] = protos_g[tid];                 // exactly 256
    __syncthreads();
    int w = tid >> 5, lane = tid & 31;
    int n = blockIdx.x * 8 + w;
    if (n >= N) return;
    float v0 = emb[n*EE + lane];
    float v1 = emb[n*EE + 32 + lane];
    float s = v0*v0 + v1*v1;
    #pragma unroll
    for (int off = 16; off; off >>= 1) s += __shfl_xor_sync(0xffffffffu, s, off);
    float inv = 1.0f / fmaxf(sqrtf(s), 1e-12f);
    float h0 = v0 * inv, h1 = v1 * inv;
    items_out[n*EE + lane]      = h0;
    items_out[n*EE + 32 + lane] = h1;
    float d[KP];
    #pragma unroll
    for (int k = 0; k < KP; k++) {
        float dk = h0 * ps[k*EE + lane] + h1 * ps[k*EE + 32 + lane];
        #pragma unroll
        for (int off = 16; off; off >>= 1) dk += __shfl_xor_sync(0xffffffffu, dk, off);
        d[k] = dk;                            // TAU = 1
    }
    if (lane == 0) {
        float m = fmaxf(fmaxf(d[0], d[1]), fmaxf(d[2], d[3]));
        float e0 = expf(d[0]-m), e1 = expf(d[1]-m), e2 = expf(d[2]-m), e3 = expf(d[3]-m);
        float is = 1.0f / (e0+e1+e2+e3);
        *(float4*)&cates_out[n*KP] = make_float4(e0*is, e1*is, e2*is, e3*is);
    }
}

// ---------------- k2: inverse row norms of Y[kb,n] = x[b,n]*c[n,k] ----------------
__global__ void __launch_bounds__(256) rnorm_k(
        const float* __restrict__ x, const float* __restrict__ cates,
        float* __restrict__ rn, int N)
{
    __shared__ float red[8][KP];
    int b = blockIdx.x, tid = threadIdx.x;
    float s0=0.f, s1=0.f, s2=0.f, s3=0.f;
    const float* xr = x + (size_t)b * N;
    for (int n = tid; n < N; n += 256) {
        float xv = xr[n];
        float4 c = *(const float4*)&cates[n*KP];
        float t0 = xv*c.x, t1 = xv*c.y, t2 = xv*c.z, t3 = xv*c.w;
        s0 += t0*t0; s1 += t1*t1; s2 += t2*t2; s3 += t3*t3;
    }
    #pragma unroll
    for (int off = 16; off; off >>= 1) {
        s0 += __shfl_xor_sync(0xffffffffu, s0, off);
        s1 += __shfl_xor_sync(0xffffffffu, s1, off);
        s2 += __shfl_xor_sync(0xffffffffu, s2, off);
        s3 += __shfl_xor_sync(0xffffffffu, s3, off);
    }
    int w = tid >> 5;
    if ((tid & 31) == 0) { red[w][0]=s0; red[w][1]=s1; red[w][2]=s2; red[w][3]=s3; }
    __syncthreads();
    if (tid < KP) {
        float t = 0.f;
        #pragma unroll
        for (int i = 0; i < 8; i++) t += red[i][tid];
        rn[tid*BB + b] = 1.0f / fmaxf(sqrtf(t), 1e-12f);
    }
}

// ---------------- k3/k4: C[8192,128] = A[8192,8192] @ B  (generic B strides) ----------------
// B element (n,o) at Bp[n*ldn + o*ldo]
__global__ void __launch_bounds__(256) sgemm64x128(
        const float* __restrict__ A, const float* __restrict__ Bp,
        float* __restrict__ C, int Kdim, int ldn, int ldo)
{
    __shared__ float As[16][68];
    __shared__ float Bs[16][128];
    int tid = threadIdx.x;
    int tx = tid & 15, ty = tid >> 4;
    int m0 = blockIdx.x * 64;
    int cg = tid & 3, r = tid >> 2;           // A-loader coords
    bool brow = (ldo == 1);
    float acc[4][8];
    #pragma unroll
    for (int i = 0; i < 4; i++)
        #pragma unroll
        for (int j = 0; j < 8; j++) acc[i][j] = 0.f;

    for (int kc = 0; kc < Kdim; kc += 16) {
        float4 av = *(const float4*)(A + (size_t)(m0 + r) * Kdim + kc + cg*4);
        As[cg*4+0][r] = av.x; As[cg*4+1][r] = av.y;
        As[cg*4+2][r] = av.z; As[cg*4+3][r] = av.w;
        if (brow) {
            #pragma unroll
            for (int i = 0; i < 8; i++) {
                int idx = tid + i*256;
                int kk = idx >> 7, o = idx & 127;
                Bs[kk][o] = Bp[(size_t)(kc+kk)*ldn + o];
            }
        } else {
            #pragma unroll
            for (int i = 0; i < 8; i++) {
                int idx = tid + i*256;
                int o = idx >> 4, kk = idx & 15;
                Bs[kk][o] = Bp[(size_t)(kc+kk) + (size_t)o*ldo];
            }
        }
        __syncthreads();
        #pragma unroll
        for (int kk = 0; kk < 16; kk++) {
            float4 a  = *(const float4*)&As[kk][ty*4];
            float4 b0 = *(const float4*)&Bs[kk][tx*8];
            float4 b1 = *(const float4*)&Bs[kk][tx*8+4];
            float aw[4] = {a.x, a.y, a.z, a.w};
            float bw[8] = {b0.x,b0.y,b0.z,b0.w,b1.x,b1.y,b1.z,b1.w};
            #pragma unroll
            for (int i = 0; i < 4; i++)
                #pragma unroll
                for (int j = 0; j < 8; j++) acc[i][j] += aw[i]*bw[j];
        }
        __syncthreads();
    }
    #pragma unroll
    for (int i = 0; i < 4; i++) {
        int row = m0 + ty*4 + i;
        *(float4*)&C[(size_t)row*TWOE + tx*8]     = make_float4(acc[i][0],acc[i][1],acc[i][2],acc[i][3]);
        *(float4*)&C[(size_t)row*TWOE + tx*8 + 4] = make_float4(acc[i][4],acc[i][5],acc[i][6],acc[i][7]);
    }
}

// ---------------- k5: M = 0.5*(P2 + W^T) ----------------
__global__ void makeM_k(const float* __restrict__ P2, const float* __restrict__ W,
                        float* __restrict__ M)
{
    int i = blockIdx.x * 256 + threadIdx.x;     // i < NI*128
    int n = i >> 7, o = i & 127;
    M[i] = 0.5f * (P2[i] + W[(size_t)o*NI + n]);
}

// ---------------- k6: partial h GEMM:  part[c,kb,o] = sum_{n in chunk} x[b,n]*c[n,k]*M[n,o] ----
// grid: (8, nchunks). Each x-block: one k_proto and a 64-wide b range.
__global__ void __launch_bounds__(256) hpart_k(
        const float* __restrict__ x, const float* __restrict__ cates,
        const float* __restrict__ Mp, float* __restrict__ part,
        int N, int ldn, int ldo)
{
    __shared__ float Ys[16][68];
    __shared__ float Ms[16][128];
    int tid = threadIdx.x;
    int tx = tid & 15, ty = tid >> 4;
    int kproto = blockIdx.x >> 1;
    int b0 = (blockIdx.x & 1) * 64;
    int chunk = blockIdx.y;
    bool brow = (ldo == 1);
    float acc[4][8];
    #pragma unroll
    for (int i = 0; i < 4; i++)
        #pragma unroll
        for (int j = 0; j < 8; j++) acc[i][j] = 0.f;

    for (int step = 0; step < 32; step++) {
        int n0 = chunk*512 + step*16;
        #pragma unroll
        for (int i = 0; i < 4; i++) {
            int idx = tid + i*256;               // < 1024
            int nn = idx & 15, bb = idx >> 4;
            int n = n0 + nn;
            Ys[nn][bb] = x[(size_t)(b0+bb)*N + n] * cates[n*KP + kproto];
        }
        if (brow) {
            #pragma unroll
            for (int i = 0; i < 8; i++) {
                int idx = tid + i*256;
                int kk = idx >> 7, o = idx & 127;
                Ms[kk][o] = Mp[(size_t)(n0+kk)*ldn + o];
            }
        } else {
            #pragma unroll
            for (int i = 0; i < 8; i++) {
                int idx = tid + i*256;
                int o = idx >> 4, kk = idx & 15;
                Ms[kk][o] = Mp[(size_t)(n0+kk) + (size_t)o*ldo];
            }
        }
        __syncthreads();
        #pragma unroll
        for (int kk = 0; kk < 16; kk++) {
            float4 a  = *(const float4*)&Ys[kk][ty*4];
            float4 m0v = *(const float4*)&Ms[kk][tx*8];
            float4 m1v = *(const float4*)&Ms[kk][tx*8+4];
            float aw[4] = {a.x, a.y, a.z, a.w};
            float bw[8] = {m0v.x,m0v.y,m0v.z,m0v.w,m1v.x,m1v.y,m1v.z,m1v.w};
            #pragma unroll
            for (int i = 0; i < 4; i++)
                #pragma unroll
                for (int j = 0; j < 8; j++) acc[i][j] += aw[i]*bw[j];
        }
        __syncthreads();
    }
    #pragma unroll
    for (int i = 0; i < 4; i++) {
        int kb = kproto*BB + b0 + ty*4 + i;     // 0..511
        float* p = &part[(size_t)chunk*512*TWOE + (size_t)kb*TWOE + tx*8];
        *(float4*)p       = make_float4(acc[i][0],acc[i][1],acc[i][2],acc[i][3]);
        *(float4*)(p + 4) = make_float4(acc[i][4],acc[i][5],acc[i][6],acc[i][7]);
    }
}

// ---------------- k7: reduce partials, add bias, split mu (l2-normalized) / logvar ----------
__global__ void __launch_bounds__(128) hfinal_k(
        const float* __restrict__ part, int nchunks,
        const float* __restrict__ rn, const float* __restrict__ bias,
        float* __restrict__ out_mu, float* __restrict__ out_lv)
{
    __shared__ float sq[64];
    __shared__ float sinv;
    int kb = blockIdx.x, o = threadIdx.x;
    float s = 0.f;
    for (int c = 0; c < nchunks; c++) s += part[(size_t)c*512*TWOE + (size_t)kb*TWOE + o];
    float h = s * rn[kb] + bias[o];
    if (o < 64) sq[o] = h*h;
    __syncthreads();
    if (o == 0) {
        float t = 0.f;
        #pragma unroll
        for (int i = 0; i < 64; i++) t += sq[i];
        sinv = 1.0f / fmaxf(sqrtf(t), 1e-12f);
    }
    __syncthreads();
    if (o < 64) out_mu[(size_t)kb*EE + o] = h * sinv;
    else        out_lv[(size_t)kb*EE + (o-64)] = -h;
}

// ---------------- k8: decoder  out[b,n] = log( sum_k exp(mu_kb . item_n) * c[n,k] ) -------
// grid: (N/64, 128/16). block 256 = (tx: 16 groups of 4 n) x (ty: 16 b)
__global__ void __launch_bounds__(256) decoder_k(
        const float* __restrict__ items, const float* __restrict__ cates,
        const float* __restrict__ mu, float* __restrict__ out, int N)
{
    __shared__ float itemsT[64][68];     // [e][n]
    __shared__ float mu_s[KP][16][64];   // [k][b][e]
    __shared__ float cs[64][4];
    int tid = threadIdx.x;
    int tx = tid & 15, ty = tid >> 4;
    int n0 = blockIdx.x * 64;
    int bt = blockIdx.y * 16;
    #pragma unroll
    for (int i = 0; i < 16; i++) {
        int idx = tid + i*256;           // < 4096
        int n = idx >> 6, e = idx & 63;
        itemsT[e][n] = items[(size_t)(n0+n)*EE + e];
    }
    #pragma unroll
    for (int i = 0; i < 16; i++) {
        int idx = tid + i*256;           // < 4096
        int kb = idx >> 6, e = idx & 63;
        int k = kb >> 4, b = kb & 15;
        mu_s[k][b][e] = mu[(size_t)(k*BB + bt + b)*EE + e];
    }
    if (tid < 256) {
        int n = tid >> 2, kk = tid & 3;
        cs[n][kk] = cates[(size_t)(n0+n)*KP + kk];
    }
    __syncthreads();

    float acc[4][KP];
    #pragma unroll
    for (int i = 0; i < 4; i++)
        #pragma unroll
        for (int k = 0; k < KP; k++) acc[i][k] = 0.f;

    #pragma unroll 4
    for (int e = 0; e < 64; e++) {
        float4 a = *(const float4*)&itemsT[e][tx*4];
        float aw[4] = {a.x, a.y, a.z, a.w};
        float m0 = mu_s[0][ty][e], m1 = mu_s[1][ty][e];
        float m2 = mu_s[2][ty][e], m3 = mu_s[3][ty][e];
        #pragma unroll
        for (int i = 0; i < 4; i++) {
            acc[i][0] += aw[i]*m0; acc[i][1] += aw[i]*m1;
            acc[i][2] += aw[i]*m2; acc[i][3] += aw[i]*m3;
        }
    }
    int b = bt + ty;
    #pragma unroll
    for (int i = 0; i < 4; i++) {
        int nl = tx*4 + i;
        float4 c = *(const float4*)&cs[nl][0];
        float p = expf(acc[i][0])*c.x + expf(acc[i][1])*c.y
                + expf(acc[i][2])*c.z + expf(acc[i][3])*c.w;
        out[(size_t)b*N + n0 + nl] = logf(p);
    }
}

// ---------------- launch ----------------
extern "C" void kernel_launch(void* const* d_in, const int* in_sizes, int n_in,
                              void* d_out, int out_size)
{
    const float* x_cf    = (const float*)d_in[0];   // [128, 8192]
    const float* x_tx    = (const float*)d_in[1];   // [128, 16384]
    const float* adj     = (const float*)d_in[2];   // [8192, 8192]
    const float* cf_emb  = (const float*)d_in[3];   // [8192, 64]
    const float* cf_prot = (const float*)d_in[4];   // [4, 64]
    const float* cf_W    = (const float*)d_in[5];   // [128, 8192]
    const float* cf_b    = (const float*)d_in[6];   // [128]
    const float* tx_emb  = (const float*)d_in[7];   // [16384, 64]
    const float* tx_prot = (const float*)d_in[8];   // [4, 64]
    const float* tx_W    = (const float*)d_in[9];   // [128, 16384]
    const float* tx_b    = (const float*)d_in[10];  // [128]
    float* out = (float*)d_out;

    float *p_protos_cf, *p_protos_tx, *p_items_cf, *p_items_tx;
    float *p_cates_cf, *p_cates_tx, *p_rn_cf, *p_rn_tx;
    float *p_P1, *p_P2, *p_M, *p_part_cf, *p_part_tx;
    cudaGetSymbolAddress((void**)&p_protos_cf, g_protos_cf);
    cudaGetSymbolAddress((void**)&p_protos_tx, g_protos_tx);
    cudaGetSymbolAddress((void**)&p_items_cf,  g_items_cf);
    cudaGetSymbolAddress((void**)&p_items_tx,  g_items_tx);
    cudaGetSymbolAddress((void**)&p_cates_cf,  g_cates_cf);
    cudaGetSymbolAddress((void**)&p_cates_tx,  g_cates_tx);
    cudaGetSymbolAddress((void**)&p_rn_cf,     g_rnorm_cf);
    cudaGetSymbolAddress((void**)&p_rn_tx,     g_rnorm_tx);
    cudaGetSymbolAddress((void**)&p_P1,        g_P1);
    cudaGetSymbolAddress((void**)&p_P2,        g_P2);
    cudaGetSymbolAddress((void**)&p_M,         g_M);
    cudaGetSymbolAddress((void**)&p_part_cf,   g_part_cf);
    cudaGetSymbolAddress((void**)&p_part_tx,   g_part_tx);

    // 0) normalize prototypes (both branches)
    proto_norm_k<<<1, 256>>>(cf_prot, tx_prot);
    // 1) item/word embedding normalization + cates softmax
    items_cates_k<<<NI/8, 256>>>(cf_emb, p_protos_cf, p_items_cf, p_cates_cf, NI);
    items_cates_k<<<NW/8, 256>>>(tx_emb, p_protos_tx, p_items_tx, p_cates_tx, NW);
    // 2) inverse norms of xk rows
    rnorm_k<<<BB, 256>>>(x_cf, p_cates_cf, p_rn_cf, NI);
    rnorm_k<<<BB, 256>>>(x_tx, p_cates_tx, p_rn_tx, NW);
    // 3) P1 = A @ W^T        (B(n,o) = cf_W[o*8192 + n])
    sgemm64x128<<<NI/64, 256>>>(adj, cf_W, p_P1, NI, 1, NI);
    // 4) P2 = A @ P1         (row-major B)
    sgemm64x128<<<NI/64, 256>>>(adj, p_P1, p_P2, NI, TWOE, 1);
    // 5) M = 0.5*(P2 + W^T)
    makeM_k<<<NI*TWOE/256, 256>>>(p_P2, cf_W, p_M);
    // 6) h partials: cf uses M (row-major), txt uses W^T (strided)
    hpart_k<<<dim3(8, 16), 256>>>(x_cf, p_cates_cf, p_M,  p_part_cf, NI, TWOE, 1);
    hpart_k<<<dim3(8, 32), 256>>>(x_tx, p_cates_tx, tx_W, p_part_tx, NW, 1, NW);
    // 7) finalize h -> mu (normalized) + logvar, written straight into d_out
    hfinal_k<<<KP*BB, 128>>>(p_part_cf, 16, p_rn_cf, cf_b, out + OUT_CFMU, out + OUT_CFLV);
    hfinal_k<<<KP*BB, 128>>>(p_part_tx, 32, p_rn_tx, tx_b, out + OUT_TXMU, out + OUT_TXLV);
    // 8) decoder logits
    decoder_k<<<dim3(NI/64, BB/16), 256>>>(p_items_cf, p_cates_cf, out + OUT_CFMU, out + OUT_RATING, NI);
    decoder_k<<<dim3(NW/64, BB/16), 256>>>(p_items_tx, p_cates_tx, out + OUT_TXMU, out + OUT_TEXT,  NW);
}

// round 3
// speedup vs baseline: 5.1592x; 5.1592x over previous
#include <cuda_runtime.h>
#include <math.h>
#include <stdint.h>

// ---------------- problem constants ----------------
#define BB    128        // batch
#define NI    8192       // items
#define NW    16384      // words
#define EE    64         // embedding
#define KP    4          // prototypes
#define TWOE  128

// output layout (floats, concatenated)
#define OUT_RATING  0
#define OUT_TEXT    (128*8192)
#define OUT_CFMU    (OUT_TEXT + 128*16384)
#define OUT_CFLV    (OUT_CFMU + 4*128*64)
#define OUT_TXMU    (OUT_CFLV + 4*128*64)
#define OUT_TXLV    (OUT_TXMU + 4*128*64)

// ---------------- scratch (static device memory; no allocations) ----------------
__device__ float g_protos_cf[KP*EE];
__device__ float g_protos_tx[KP*EE];
__device__ float g_items_cf[NI*EE];
__device__ float g_items_tx[NW*EE];
__device__ float g_cates_cf[NI*KP];
__device__ float g_cates_tx[NW*KP];
__device__ float g_ctT_cf[KP*NI];          // cates transposed [k][n]
__device__ float g_ctT_tx[KP*NW];
__device__ float g_rnorm_cf[KP*BB];
__device__ float g_rnorm_tx[KP*BB];
__device__ float g_P1[NI*TWOE];
__device__ float g_M [NI*TWOE];
__device__ float g_bigpart[8*NI*TWOE];     // split-K partials for P1/P2 (33.5 MB)
__device__ float g_part_cf[32*512*TWOE];   // split-K partials for h (cf)
__device__ float g_part_tx[32*512*TWOE];   // split-K partials for h (tx)

// ---------------- k0: normalize prototype embeddings ----------------
__global__ void proto_norm_k(const float* __restrict__ cfp, const float* __restrict__ txp) {
    int tid = threadIdx.x;
    int w = tid >> 5, lane = tid & 31;
    const float* src = (w < 4) ? cfp : txp;
    float* dst = (w < 4) ? g_protos_cf : g_protos_tx;
    int row = w & 3;
    float v0 = src[row*EE + lane];
    float v1 = src[row*EE + 32 + lane];
    float s = v0*v0 + v1*v1;
    #pragma unroll
    for (int off = 16; off; off >>= 1) s += __shfl_xor_sync(0xffffffffu, s, off);
    float inv = 1.0f / fmaxf(sqrtf(s), 1e-12f);
    dst[row*EE + lane]      = v0 * inv;
    dst[row*EE + 32 + lane] = v1 * inv;
}

// ---------------- k1: normalize item embeddings + cates softmax (+ transposed copy) ----
__global__ void __launch_bounds__(256) items_cates_k(
        const float* __restrict__ emb, const float* __restrict__ protos_g,
        float* __restrict__ items_out, float* __restrict__ cates_out,
        float* __restrict__ catesT_out, int N)
{
    __shared__ float ps[KP*EE];
    int tid = threadIdx.x;
    ps[tid] = protos_g[tid];
    __syncthreads();
    int w = tid >> 5, lane = tid & 31;
    int n = blockIdx.x * 8 + w;
    if (n >= N) return;
    float v0 = emb[n*EE + lane];
    float v1 = emb[n*EE + 32 + lane];
    float s = v0*v0 + v1*v1;
    #pragma unroll
    for (int off = 16; off; off >>= 1) s += __shfl_xor_sync(0xffffffffu, s, off);
    float inv = 1.0f / fmaxf(sqrtf(s), 1e-12f);
    float h0 = v0 * inv, h1 = v1 * inv;
    items_out[n*EE + lane]      = h0;
    items_out[n*EE + 32 + lane] = h1;
    float d[KP];
    #pragma unroll
    for (int k = 0; k < KP; k++) {
        float dk = h0 * ps[k*EE + lane] + h1 * ps[k*EE + 32 + lane];
        #pragma unroll
        for (int off = 16; off; off >>= 1) dk += __shfl_xor_sync(0xffffffffu, dk, off);
        d[k] = dk;
    }
    if (lane == 0) {
        float m = fmaxf(fmaxf(d[0], d[1]), fmaxf(d[2], d[3]));
        float e0 = __expf(d[0]-m), e1 = __expf(d[1]-m), e2 = __expf(d[2]-m), e3 = __expf(d[3]-m);
        float is = 1.0f / (e0+e1+e2+e3);
        float c0 = e0*is, c1 = e1*is, c2 = e2*is, c3 = e3*is;
        *(float4*)&cates_out[n*KP] = make_float4(c0, c1, c2, c3);
        catesT_out[0*N + n] = c0;
        catesT_out[1*N + n] = c1;
        catesT_out[2*N + n] = c2;
        catesT_out[3*N + n] = c3;
    }
}

// ---------------- k2: inverse row norms of Y[kb,n] = x[b,n]*c[n,k] ----------------
__global__ void __launch_bounds__(256) rnorm_k(
        const float* __restrict__ x, const float* __restrict__ cates,
        float* __restrict__ rn, int N)
{
    __shared__ float red[8][KP];
    int b = blockIdx.x, tid = threadIdx.x;
    float s0=0.f, s1=0.f, s2=0.f, s3=0.f;
    const float* xr = x + (size_t)b * N;
    for (int n = tid; n < N; n += 256) {
        float xv = xr[n];
        float4 c = *(const float4*)&cates[n*KP];
        float t0 = xv*c.x, t1 = xv*c.y, t2 = xv*c.z, t3 = xv*c.w;
        s0 += t0*t0; s1 += t1*t1; s2 += t2*t2; s3 += t3*t3;
    }
    #pragma unroll
    for (int off = 16; off; off >>= 1) {
        s0 += __shfl_xor_sync(0xffffffffu, s0, off);
        s1 += __shfl_xor_sync(0xffffffffu, s1, off);
        s2 += __shfl_xor_sync(0xffffffffu, s2, off);
        s3 += __shfl_xor_sync(0xffffffffu, s3, off);
    }
    int w = tid >> 5;
    if ((tid & 31) == 0) { red[w][0]=s0; red[w][1]=s1; red[w][2]=s2; red[w][3]=s3; }
    __syncthreads();
    if (tid < KP) {
        float t = 0.f;
        #pragma unroll
        for (int i = 0; i < 8; i++) t += red[i][tid];
        rn[tid*BB + b] = 1.0f / fmaxf(sqrtf(t), 1e-12f);
    }
}

// ---------------- TF32 helpers ----------------
__device__ __forceinline__ uint32_t f2tf(float f) {
    uint32_t r;
    asm("cvt.rna.tf32.f32 %0, %1;" : "=r"(r) : "f"(f));
    return r;
}
__device__ __forceinline__ void mma_tf32(float c[4], const uint32_t a[4],
                                         uint32_t b0, uint32_t b1) {
    asm volatile(
        "mma.sync.aligned.m16n8k8.row.col.f32.tf32.tf32.f32 "
        "{%0,%1,%2,%3}, {%4,%5,%6,%7}, {%8,%9}, {%0,%1,%2,%3};"
        : "+f"(c[0]), "+f"(c[1]), "+f"(c[2]), "+f"(c[3])
        : "r"(a[0]), "r"(a[1]), "r"(a[2]), "r"(a[3]), "r"(b0), "r"(b1));
}

// ---------------- TF32 MMA GEMM, 128x128 tile, BLK_K=16, split-K partials ----------------
// amode 0: A row-major [m][Ktot]        (m global = blockIdx.x*128 + m_local)
// amode 1: A[m][n] = x[m_local][n] * ctT[blockIdx.x][n]   (hpart: Y generated on the fly)
// bmode 0: B row-major [k][128]
// bmode 1: B[k][o] = W[o][k]  (W row length = Ktot)
// output: part[(blockIdx.z*Mrows + m)*128 + o]
#define AS_LD 20
#define BS_LD 136
__global__ void __launch_bounds__(256) mma_gemm_k(
        const float* __restrict__ A, const float* __restrict__ ctT,
        const float* __restrict__ B, float* __restrict__ part,
        int Mrows, int Ktot, int Ksplit, int amode, int bmode)
{
    __shared__ float As[2][128][AS_LD];
    __shared__ float Bs[2][16][BS_LD];
    int tid = threadIdx.x;
    int lane = tid & 31, w = tid >> 5;
    int wm = w & 3, wn = w >> 2;          // 4 warps along M, 2 along N
    int lr = lane >> 2, lc = lane & 3;
    int m0 = blockIdx.x * 128;
    int kc0 = blockIdx.z * Ksplit;
    int niter = Ksplit / 16;
    const float* ctb = (amode == 1) ? (ctT + (size_t)blockIdx.x * Ktot) : A;

    float acc[2][8][4];
    #pragma unroll
    for (int mt = 0; mt < 2; mt++)
        #pragma unroll
        for (int nt = 0; nt < 8; nt++)
            #pragma unroll
            for (int i = 0; i < 4; i++) acc[mt][nt][i] = 0.f;

    float4 ra[2], rb[2];

    auto ldA = [&](int kc) {
        #pragma unroll
        for (int i = 0; i < 2; i++) {
            int idx = tid + i*256;
            int m = idx >> 2, kq = (idx & 3) * 4;
            if (amode == 0) {
                ra[i] = *(const float4*)(A + (size_t)(m0 + m) * Ktot + kc + kq);
            } else {
                float4 v = *(const float4*)(A + (size_t)m * Ktot + kc + kq);
                float4 c = *(const float4*)(ctb + kc + kq);
                v.x *= c.x; v.y *= c.y; v.z *= c.z; v.w *= c.w;
                ra[i] = v;
            }
        }
    };
    auto stA = [&](int buf) {
        #pragma unroll
        for (int i = 0; i < 2; i++) {
            int idx = tid + i*256;
            int m = idx >> 2, kq = (idx & 3) * 4;
            *(float4*)&As[buf][m][kq] = ra[i];
        }
    };
    auto ldB = [&](int kc) {
        if (bmode == 0) {
            #pragma unroll
            for (int i = 0; i < 2; i++) {
                int idx = tid + i*256;
                int k = idx >> 5, oq = (idx & 31) * 4;
                rb[i] = *(const float4*)(B + (size_t)(kc + k) * 128 + oq);
            }
        } else {
            int o = tid >> 1;
            #pragma unroll
            for (int i = 0; i < 2; i++) {
                int kq = (tid & 1) * 8 + i * 4;
                rb[i] = *(const float4*)(B + (size_t)o * Ktot + kc + kq);
            }
        }
    };
    auto stB = [&](int buf) {
        if (bmode == 0) {
            #pragma unroll
            for (int i = 0; i < 2; i++) {
                int idx = tid + i*256;
                int k = idx >> 5, oq = (idx & 31) * 4;
                *(float4*)&Bs[buf][k][oq] = rb[i];
            }
        } else {
            int o = tid >> 1;
            #pragma unroll
            for (int i = 0; i < 2; i++) {
                int kq = (tid & 1) * 8 + i * 4;
                Bs[buf][kq+0][o] = rb[i].x;
                Bs[buf][kq+1][o] = rb[i].y;
                Bs[buf][kq+2][o] = rb[i].z;
                Bs[buf][kq+3][o] = rb[i].w;
            }
        }
    };
    auto compute = [&](int buf) {
        #pragma unroll
        for (int ks = 0; ks < 2; ks++) {
            int k0 = ks * 8;
            uint32_t afr[2][4];
            #pragma unroll
            for (int mt = 0; mt < 2; mt++) {
                int mrow = wm*32 + mt*16 + lr;
                afr[mt][0] = f2tf(As[buf][mrow  ][k0+lc  ]);
                afr[mt][1] = f2tf(As[buf][mrow+8][k0+lc  ]);
                afr[mt][2] = f2tf(As[buf][mrow  ][k0+lc+4]);
                afr[mt][3] = f2tf(As[buf][mrow+8][k0+lc+4]);
            }
            #pragma unroll
            for (int nt = 0; nt < 8; nt++) {
                int o = wn*64 + nt*8 + lr;
                uint32_t b0 = f2tf(Bs[buf][k0+lc  ][o]);
                uint32_t b1 = f2tf(Bs[buf][k0+lc+4][o]);
                mma_tf32(acc[0][nt], afr[0], b0, b1);
                mma_tf32(acc[1][nt], afr[1], b0, b1);
            }
        }
    };

    ldA(kc0); ldB(kc0); stA(0); stB(0);
    __syncthreads();
    for (int it = 0; it < niter; it++) {
        int cur = it & 1;
        if (it + 1 < niter) { ldA(kc0 + (it+1)*16); ldB(kc0 + (it+1)*16); }
        compute(cur);
        if (it + 1 < niter) { stA(1-cur); stB(1-cur); }
        __syncthreads();
    }

    #pragma unroll
    for (int mt = 0; mt < 2; mt++)
        #pragma unroll
        for (int nt = 0; nt < 8; nt++) {
            int row = m0 + wm*32 + mt*16 + lr;
            int col = wn*64 + nt*8 + lc*2;
            float* p = part + ((size_t)blockIdx.z * Mrows + row) * TWOE + col;
            *(float2*)p             = make_float2(acc[mt][nt][0], acc[mt][nt][1]);
            *(float2*)(p + 8*TWOE)  = make_float2(acc[mt][nt][2], acc[mt][nt][3]);
        }
}

// ---------------- reduce split-K partials (plain) ----------------
__global__ void reduce8_k(const float* __restrict__ part, float* __restrict__ out,
                          int stride4, int total4)
{
    int i = blockIdx.x * 256 + threadIdx.x;
    if (i >= total4) return;
    const float4* p4 = (const float4*)part;
    float4 s = p4[i];
    #pragma unroll
    for (int z = 1; z < 8; z++) {
        float4 v = p4[(size_t)z * stride4 + i];
        s.x += v.x; s.y += v.y; s.z += v.z; s.w += v.w;
    }
    ((float4*)out)[i] = s;
}

// ---------------- reduce P2 partials + combine with W^T: M = 0.5*(P2 + W^T) ----------
__global__ void reduceM_k(const float* __restrict__ part, const float* __restrict__ W,
                          float* __restrict__ M)
{
    int i = blockIdx.x * 256 + threadIdx.x;       // < NI*128
    float s = 0.f;
    #pragma unroll
    for (int z = 0; z < 8; z++) s += part[(size_t)z * (NI*TWOE) + i];
    int n = i >> 7, o = i & 127;
    M[i] = 0.5f * (s + W[(size_t)o * NI + n]);
}

// ---------------- finalize h -> mu (normalized) + logvar ----------------
__global__ void __launch_bounds__(128) hfinal_k(
        const float* __restrict__ part, int nchunks,
        const float* __restrict__ rn, const float* __restrict__ bias,
        float* __restrict__ out_mu, float* __restrict__ out_lv)
{
    __shared__ float sq[64];
    __shared__ float sinv;
    int kb = blockIdx.x, o = threadIdx.x;
    float s = 0.f;
    for (int c = 0; c < nchunks; c++) s += part[(size_t)c*512*TWOE + (size_t)kb*TWOE + o];
    float h = s * rn[kb] + bias[o];
    if (o < 64) sq[o] = h*h;
    __syncthreads();
    if (o == 0) {
        float t = 0.f;
        #pragma unroll
        for (int i = 0; i < 64; i++) t += sq[i];
        sinv = 1.0f / fmaxf(sqrtf(t), 1e-12f);
    }
    __syncthreads();
    if (o < 64) out_mu[(size_t)kb*EE + o] = h * sinv;
    else        out_lv[(size_t)kb*EE + (o-64)] = -h;
}

// ---------------- decoder  out[b,n] = log( sum_k exp(mu_kb . item_n) * c[n,k] ) -------
__global__ void __launch_bounds__(256) decoder_k(
        const float* __restrict__ items, const float* __restrict__ cates,
        const float* __restrict__ mu, float* __restrict__ out, int N)
{
    __shared__ float itemsT[64][68];
    __shared__ float mu_s[KP][16][64];
    __shared__ float cs[64][4];
    int tid = threadIdx.x;
    int tx = tid & 15, ty = tid >> 4;
    int n0 = blockIdx.x * 64;
    int bt = blockIdx.y * 16;
    #pragma unroll
    for (int i = 0; i < 16; i++) {
        int idx = tid + i*256;
        int n = idx >> 6, e = idx & 63;
        itemsT[e][n] = items[(size_t)(n0+n)*EE + e];
    }
    #pragma unroll
    for (int i = 0; i < 16; i++) {
        int idx = tid + i*256;
        int kb = idx >> 6, e = idx & 63;
        int k = kb >> 4, b = kb & 15;
        mu_s[k][b][e] = mu[(size_t)(k*BB + bt + b)*EE + e];
    }
    {
        int n = tid >> 2, kk = tid & 3;
        cs[n][kk] = cates[(size_t)(n0+n)*KP + kk];
    }
    __syncthreads();

    float acc[4][KP];
    #pragma unroll
    for (int i = 0; i < 4; i++)
        #pragma unroll
        for (int k = 0; k < KP; k++) acc[i][k] = 0.f;

    #pragma unroll 4
    for (int e = 0; e < 64; e++) {
        float4 a = *(const float4*)&itemsT[e][tx*4];
        float aw[4] = {a.x, a.y, a.z, a.w};
        float m0 = mu_s[0][ty][e], m1 = mu_s[1][ty][e];
        float m2 = mu_s[2][ty][e], m3 = mu_s[3][ty][e];
        #pragma unroll
        for (int i = 0; i < 4; i++) {
            acc[i][0] += aw[i]*m0; acc[i][1] += aw[i]*m1;
            acc[i][2] += aw[i]*m2; acc[i][3] += aw[i]*m3;
        }
    }
    int b = bt + ty;
    #pragma unroll
    for (int i = 0; i < 4; i++) {
        int nl = tx*4 + i;
        float4 c = *(const float4*)&cs[nl][0];
        float p = __expf(acc[i][0])*c.x + __expf(acc[i][1])*c.y
                + __expf(acc[i][2])*c.z + __expf(acc[i][3])*c.w;
        out[(size_t)b*N + n0 + nl] = __logf(p);
    }
}

// ---------------- launch ----------------
extern "C" void kernel_launch(void* const* d_in, const int* in_sizes, int n_in,
                              void* d_out, int out_size)
{
    const float* x_cf    = (const float*)d_in[0];
    const float* x_tx    = (const float*)d_in[1];
    const float* adj     = (const float*)d_in[2];
    const float* cf_emb  = (const float*)d_in[3];
    const float* cf_prot = (const float*)d_in[4];
    const float* cf_W    = (const float*)d_in[5];
    const float* cf_b    = (const float*)d_in[6];
    const float* tx_emb  = (const float*)d_in[7];
    const float* tx_prot = (const float*)d_in[8];
    const float* tx_W    = (const float*)d_in[9];
    const float* tx_b    = (const float*)d_in[10];
    float* out = (float*)d_out;

    float *p_protos_cf, *p_protos_tx, *p_items_cf, *p_items_tx;
    float *p_cates_cf, *p_cates_tx, *p_ctT_cf, *p_ctT_tx, *p_rn_cf, *p_rn_tx;
    float *p_P1, *p_M, *p_big, *p_part_cf, *p_part_tx;
    cudaGetSymbolAddress((void**)&p_protos_cf, g_protos_cf);
    cudaGetSymbolAddress((void**)&p_protos_tx, g_protos_tx);
    cudaGetSymbolAddress((void**)&p_items_cf,  g_items_cf);
    cudaGetSymbolAddress((void**)&p_items_tx,  g_items_tx);
    cudaGetSymbolAddress((void**)&p_cates_cf,  g_cates_cf);
    cudaGetSymbolAddress((void**)&p_cates_tx,  g_cates_tx);
    cudaGetSymbolAddress((void**)&p_ctT_cf,    g_ctT_cf);
    cudaGetSymbolAddress((void**)&p_ctT_tx,    g_ctT_tx);
    cudaGetSymbolAddress((void**)&p_rn_cf,     g_rnorm_cf);
    cudaGetSymbolAddress((void**)&p_rn_tx,     g_rnorm_tx);
    cudaGetSymbolAddress((void**)&p_P1,        g_P1);
    cudaGetSymbolAddress((void**)&p_M,         g_M);
    cudaGetSymbolAddress((void**)&p_big,       g_bigpart);
    cudaGetSymbolAddress((void**)&p_part_cf,   g_part_cf);
    cudaGetSymbolAddress((void**)&p_part_tx,   g_part_tx);

    // 0) prototypes
    proto_norm_k<<<1, 256>>>(cf_prot, tx_prot);
    // 1) items/cates (+ transposed cates)
    items_cates_k<<<NI/8, 256>>>(cf_emb, p_protos_cf, p_items_cf, p_cates_cf, p_ctT_cf, NI);
    items_cates_k<<<NW/8, 256>>>(tx_emb, p_protos_tx, p_items_tx, p_cates_tx, p_ctT_tx, NW);
    // 2) row norms
    rnorm_k<<<BB, 256>>>(x_cf, p_cates_cf, p_rn_cf, NI);
    rnorm_k<<<BB, 256>>>(x_tx, p_cates_tx, p_rn_tx, NW);
    // 3) P1 = A @ W^T  (split-K 8)
    mma_gemm_k<<<dim3(NI/128, 1, 8), 256>>>(adj, nullptr, cf_W, p_big,
                                            NI, NI, NI/8, 0, 1);
    reduce8_k<<<(NI*TWOE/4 + 255)/256, 256>>>(p_big, p_P1, NI*TWOE/4, NI*TWOE/4);
    // 4) P2 partials = A @ P1 (split-K 8), then M = 0.5*(P2 + W^T)
    mma_gemm_k<<<dim3(NI/128, 1, 8), 256>>>(adj, nullptr, p_P1, p_big,
                                            NI, NI, NI/8, 0, 0);
    reduceM_k<<<NI*TWOE/256, 256>>>(p_big, cf_W, p_M);
    // 5) h partials (Y generated on the fly), split-K 32
    mma_gemm_k<<<dim3(4, 1, 32), 256>>>(x_cf, p_ctT_cf, p_M, p_part_cf,
                                        512, NI, NI/32, 1, 0);
    mma_gemm_k<<<dim3(4, 1, 32), 256>>>(x_tx, p_ctT_tx, tx_W, p_part_tx,
                                        512, NW, NW/32, 1, 1);
    // 6) finalize h -> mu/logvar
    hfinal_k<<<KP*BB, 128>>>(p_part_cf, 32, p_rn_cf, cf_b, out + OUT_CFMU, out + OUT_CFLV);
    hfinal_k<<<KP*BB, 128>>>(p_part_tx, 32, p_rn_tx, tx_b, out + OUT_TXMU, out + OUT_TXLV);
    // 7) decoder
    decoder_k<<<dim3(NI/64, BB/16), 256>>>(p_items_cf, p_cates_cf, out + OUT_CFMU, out + OUT_RATING, NI);
    decoder_k<<<dim3(NW/64, BB/16), 256>>>(p_items_tx, p_cates_tx, out + OUT_TXMU, out + OUT_TEXT,  NW);
}

// round 4
// speedup vs baseline: 6.2957x; 1.2203x over previous
#include <cuda_runtime.h>
#include <math.h>
#include <stdint.h>

// ---------------- problem constants ----------------
#define BB    128
#define NI    8192
#define NW    16384
#define EE    64
#define KP    4
#define TWOE  128

// output layout (floats, concatenated)
#define OUT_RATING  0
#define OUT_TEXT    (128*8192)
#define OUT_CFMU    (OUT_TEXT + 128*16384)
#define OUT_CFLV    (OUT_CFMU + 4*128*64)
#define OUT_TXMU    (OUT_CFLV + 4*128*64)
#define OUT_TXLV    (OUT_TXMU + 4*128*64)

#define HSPLIT 64          // split-K for hpart GEMMs

// ---------------- scratch ----------------
__device__ float g_protos_cf[KP*EE];
__device__ float g_protos_tx[KP*EE];
__device__ float g_items_cf[NI*EE];
__device__ float g_items_tx[NW*EE];
__device__ float g_cates_cf[NI*KP];
__device__ float g_cates_tx[NW*KP];
__device__ float g_ctT_cf[KP*NI];
__device__ float g_ctT_tx[KP*NW];
__device__ float g_rnp_cf[KP*BB*8];        // rnorm partials
__device__ float g_rnp_tx[KP*BB*8];
__device__ float g_P1[NI*TWOE];
__device__ float g_M [NI*TWOE];
__device__ float g_bigpart[8*NI*TWOE];
__device__ float g_part_cf[HSPLIT*512*TWOE];
__device__ float g_part_tx[HSPLIT*512*TWOE];

// ---------------- k0: normalize prototypes ----------------
__global__ void proto_norm_k(const float* __restrict__ cfp, const float* __restrict__ txp) {
    int tid = threadIdx.x;
    int w = tid >> 5, lane = tid & 31;
    const float* src = (w < 4) ? cfp : txp;
    float* dst = (w < 4) ? g_protos_cf : g_protos_tx;
    int row = w & 3;
    float v0 = src[row*EE + lane];
    float v1 = src[row*EE + 32 + lane];
    float s = v0*v0 + v1*v1;
    #pragma unroll
    for (int off = 16; off; off >>= 1) s += __shfl_xor_sync(0xffffffffu, s, off);
    float inv = 1.0f / fmaxf(sqrtf(s), 1e-12f);
    dst[row*EE + lane]      = v0 * inv;
    dst[row*EE + 32 + lane] = v1 * inv;
}

// ---------------- k1: item norm + cates softmax (+ transposed) ----------------
__global__ void __launch_bounds__(256) items_cates_k(
        const float* __restrict__ emb, const float* __restrict__ protos_g,
        float* __restrict__ items_out, float* __restrict__ cates_out,
        float* __restrict__ catesT_out, int N)
{
    __shared__ float ps[KP*EE];
    int tid = threadIdx.x;
    ps[tid] = protos_g[tid];
    __syncthreads();
    int w = tid >> 5, lane = tid & 31;
    int n = blockIdx.x * 8 + w;
    if (n >= N) return;
    float v0 = emb[n*EE + lane];
    float v1 = emb[n*EE + 32 + lane];
    float s = v0*v0 + v1*v1;
    #pragma unroll
    for (int off = 16; off; off >>= 1) s += __shfl_xor_sync(0xffffffffu, s, off);
    float inv = 1.0f / fmaxf(sqrtf(s), 1e-12f);
    float h0 = v0 * inv, h1 = v1 * inv;
    items_out[n*EE + lane]      = h0;
    items_out[n*EE + 32 + lane] = h1;
    float d[KP];
    #pragma unroll
    for (int k = 0; k < KP; k++) {
        float dk = h0 * ps[k*EE + lane] + h1 * ps[k*EE + 32 + lane];
        #pragma unroll
        for (int off = 16; off; off >>= 1) dk += __shfl_xor_sync(0xffffffffu, dk, off);
        d[k] = dk;
    }
    if (lane == 0) {
        float m = fmaxf(fmaxf(d[0], d[1]), fmaxf(d[2], d[3]));
        float e0 = __expf(d[0]-m), e1 = __expf(d[1]-m), e2 = __expf(d[2]-m), e3 = __expf(d[3]-m);
        float is = 1.0f / (e0+e1+e2+e3);
        float c0 = e0*is, c1 = e1*is, c2 = e2*is, c3 = e3*is;
        *(float4*)&cates_out[n*KP] = make_float4(c0, c1, c2, c3);
        catesT_out[0*N + n] = c0;
        catesT_out[1*N + n] = c1;
        catesT_out[2*N + n] = c2;
        catesT_out[3*N + n] = c3;
    }
}

// ---------------- k2: rnorm partials over 8 n-chunks ----------------
__global__ void __launch_bounds__(256) rnormp_k(
        const float* __restrict__ x, const float* __restrict__ cates,
        float* __restrict__ rnp, int N)
{
    __shared__ float red[8][KP];
    int b = blockIdx.x, chunk = blockIdx.y, tid = threadIdx.x;
    int n0 = chunk * (N >> 3), n1 = n0 + (N >> 3);
    float s0=0.f, s1=0.f, s2=0.f, s3=0.f;
    const float* xr = x + (size_t)b * N;
    for (int n = n0 + tid; n < n1; n += 256) {
        float xv = xr[n];
        float4 c = *(const float4*)&cates[n*KP];
        float t0 = xv*c.x, t1 = xv*c.y, t2 = xv*c.z, t3 = xv*c.w;
        s0 += t0*t0; s1 += t1*t1; s2 += t2*t2; s3 += t3*t3;
    }
    #pragma unroll
    for (int off = 16; off; off >>= 1) {
        s0 += __shfl_xor_sync(0xffffffffu, s0, off);
        s1 += __shfl_xor_sync(0xffffffffu, s1, off);
        s2 += __shfl_xor_sync(0xffffffffu, s2, off);
        s3 += __shfl_xor_sync(0xffffffffu, s3, off);
    }
    int w = tid >> 5;
    if ((tid & 31) == 0) { red[w][0]=s0; red[w][1]=s1; red[w][2]=s2; red[w][3]=s3; }
    __syncthreads();
    if (tid < KP) {
        float t = 0.f;
        #pragma unroll
        for (int i = 0; i < 8; i++) t += red[i][tid];
        rnp[(tid*BB + b)*8 + chunk] = t;
    }
}

// ---------------- TF32 helpers ----------------
__device__ __forceinline__ uint32_t f2tf(float f) {
    uint32_t r;
    asm("cvt.rna.tf32.f32 %0, %1;" : "=r"(r) : "f"(f));
    return r;
}
__device__ __forceinline__ void mma_tf32(float c[4], const uint32_t a[4],
                                         uint32_t b0, uint32_t b1) {
    asm volatile(
        "mma.sync.aligned.m16n8k8.row.col.f32.tf32.tf32.f32 "
        "{%0,%1,%2,%3}, {%4,%5,%6,%7}, {%8,%9}, {%0,%1,%2,%3};"
        : "+f"(c[0]), "+f"(c[1]), "+f"(c[2]), "+f"(c[3])
        : "r"(a[0]), "r"(a[1]), "r"(a[2]), "r"(a[3]), "r"(b0), "r"(b1));
}

// ---------------- TF32 MMA GEMM, 128x128 tile, smem holds pre-converted tf32 bits ----
#define AS_LD 20
#define BS_LD 136
__global__ void __launch_bounds__(256, 2) mma_gemm_k(
        const float* __restrict__ A, const float* __restrict__ ctT,
        const float* __restrict__ B, float* __restrict__ part,
        int Mrows, int Ktot, int Ksplit, int amode, int bmode)
{
    __shared__ uint32_t As[2][128][AS_LD];
    __shared__ uint32_t Bs[2][16][BS_LD];
    int tid = threadIdx.x;
    int lane = tid & 31, w = tid >> 5;
    int wm = w & 3, wn = w >> 2;
    int lr = lane >> 2, lc = lane & 3;
    int m0 = blockIdx.x * 128;
    int kc0 = blockIdx.z * Ksplit;
    int niter = Ksplit / 16;
    const float* ctb = (amode == 1) ? (ctT + (size_t)blockIdx.x * Ktot) : A;

    float acc[2][8][4];
    #pragma unroll
    for (int mt = 0; mt < 2; mt++)
        #pragma unroll
        for (int nt = 0; nt < 8; nt++)
            #pragma unroll
            for (int i = 0; i < 4; i++) acc[mt][nt][i] = 0.f;

    float4 ra[2], rb[2];

    auto ldA = [&](int kc) {
        #pragma unroll
        for (int i = 0; i < 2; i++) {
            int idx = tid + i*256;
            int m = idx >> 2, kq = (idx & 3) * 4;
            if (amode == 0) {
                ra[i] = *(const float4*)(A + (size_t)(m0 + m) * Ktot + kc + kq);
            } else {
                float4 v = *(const float4*)(A + (size_t)m * Ktot + kc + kq);
                float4 c = *(const float4*)(ctb + kc + kq);
                v.x *= c.x; v.y *= c.y; v.z *= c.z; v.w *= c.w;
                ra[i] = v;
            }
        }
    };
    auto stA = [&](int buf) {
        #pragma unroll
        for (int i = 0; i < 2; i++) {
            int idx = tid + i*256;
            int m = idx >> 2, kq = (idx & 3) * 4;
            uint4 u;
            u.x = f2tf(ra[i].x); u.y = f2tf(ra[i].y);
            u.z = f2tf(ra[i].z); u.w = f2tf(ra[i].w);
            *(uint4*)&As[buf][m][kq] = u;
        }
    };
    auto ldB = [&](int kc) {
        if (bmode == 0) {
            #pragma unroll
            for (int i = 0; i < 2; i++) {
                int idx = tid + i*256;
                int k = idx >> 5, oq = (idx & 31) * 4;
                rb[i] = *(const float4*)(B + (size_t)(kc + k) * 128 + oq);
            }
        } else {
            int o = tid >> 1;
            #pragma unroll
            for (int i = 0; i < 2; i++) {
                int kq = (tid & 1) * 8 + i * 4;
                rb[i] = *(const float4*)(B + (size_t)o * Ktot + kc + kq);
            }
        }
    };
    auto stB = [&](int buf) {
        if (bmode == 0) {
            #pragma unroll
            for (int i = 0; i < 2; i++) {
                int idx = tid + i*256;
                int k = idx >> 5, oq = (idx & 31) * 4;
                uint4 u;
                u.x = f2tf(rb[i].x); u.y = f2tf(rb[i].y);
                u.z = f2tf(rb[i].z); u.w = f2tf(rb[i].w);
                *(uint4*)&Bs[buf][k][oq] = u;
            }
        } else {
            int o = tid >> 1;
            #pragma unroll
            for (int i = 0; i < 2; i++) {
                int kq = (tid & 1) * 8 + i * 4;
                Bs[buf][kq+0][o] = f2tf(rb[i].x);
                Bs[buf][kq+1][o] = f2tf(rb[i].y);
                Bs[buf][kq+2][o] = f2tf(rb[i].z);
                Bs[buf][kq+3][o] = f2tf(rb[i].w);
            }
        }
    };
    auto compute = [&](int buf) {
        #pragma unroll
        for (int ks = 0; ks < 2; ks++) {
            int k0 = ks * 8;
            uint32_t afr[2][4];
            #pragma unroll
            for (int mt = 0; mt < 2; mt++) {
                int mrow = wm*32 + mt*16 + lr;
                afr[mt][0] = As[buf][mrow  ][k0+lc  ];
                afr[mt][1] = As[buf][mrow+8][k0+lc  ];
                afr[mt][2] = As[buf][mrow  ][k0+lc+4];
                afr[mt][3] = As[buf][mrow+8][k0+lc+4];
            }
            #pragma unroll
            for (int nt = 0; nt < 8; nt++) {
                int o = wn*64 + nt*8 + lr;
                uint32_t b0 = Bs[buf][k0+lc  ][o];
                uint32_t b1 = Bs[buf][k0+lc+4][o];
                mma_tf32(acc[0][nt], afr[0], b0, b1);
                mma_tf32(acc[1][nt], afr[1], b0, b1);
            }
        }
    };

    ldA(kc0); ldB(kc0); stA(0); stB(0);
    __syncthreads();
    for (int it = 0; it < niter; it++) {
        int cur = it & 1;
        if (it + 1 < niter) { ldA(kc0 + (it+1)*16); ldB(kc0 + (it+1)*16); }
        compute(cur);
        if (it + 1 < niter) { stA(1-cur); stB(1-cur); }
        __syncthreads();
    }

    #pragma unroll
    for (int mt = 0; mt < 2; mt++)
        #pragma unroll
        for (int nt = 0; nt < 8; nt++) {
            int row = m0 + wm*32 + mt*16 + lr;
            int col = wn*64 + nt*8 + lc*2;
            float* p = part + ((size_t)blockIdx.z * Mrows + row) * TWOE + col;
            *(float2*)p             = make_float2(acc[mt][nt][0], acc[mt][nt][1]);
            *(float2*)(p + 8*TWOE)  = make_float2(acc[mt][nt][2], acc[mt][nt][3]);
        }
}

// ---------------- reduce split-K partials ----------------
__global__ void reduce8_k(const float* __restrict__ part, float* __restrict__ out,
                          int stride4, int total4)
{
    int i = blockIdx.x * 256 + threadIdx.x;
    if (i >= total4) return;
    const float4* p4 = (const float4*)part;
    float4 s = p4[i];
    #pragma unroll
    for (int z = 1; z < 8; z++) {
        float4 v = p4[(size_t)z * stride4 + i];
        s.x += v.x; s.y += v.y; s.z += v.z; s.w += v.w;
    }
    ((float4*)out)[i] = s;
}

__global__ void reduceM_k(const float* __restrict__ part, const float* __restrict__ W,
                          float* __restrict__ M)
{
    int i = blockIdx.x * 256 + threadIdx.x;
    float s = 0.f;
    #pragma unroll
    for (int z = 0; z < 8; z++) s += part[(size_t)z * (NI*TWOE) + i];
    int n = i >> 7, o = i & 127;
    M[i] = 0.5f * (s + W[(size_t)o * NI + n]);
}

// ---------------- finalize h -> mu / logvar (rn computed from partials) -------
__global__ void __launch_bounds__(128) hfinal_k(
        const float* __restrict__ part, int nchunks,
        const float* __restrict__ rnp, const float* __restrict__ bias,
        float* __restrict__ out_mu, float* __restrict__ out_lv)
{
    __shared__ float sq[64];
    __shared__ float sinv, s_rn;
    int kb = blockIdx.x, o = threadIdx.x;
    if (o == 0) {
        float t = 0.f;
        #pragma unroll
        for (int c = 0; c < 8; c++) t += rnp[kb*8 + c];
        s_rn = 1.0f / fmaxf(sqrtf(t), 1e-12f);
    }
    float s = 0.f;
    for (int c = 0; c < nchunks; c++) s += part[(size_t)c*512*TWOE + (size_t)kb*TWOE + o];
    __syncthreads();
    float h = s * s_rn + bias[o];
    if (o < 64) sq[o] = h*h;
    __syncthreads();
    if (o == 0) {
        float t = 0.f;
        #pragma unroll
        for (int i = 0; i < 64; i++) t += sq[i];
        sinv = 1.0f / fmaxf(sqrtf(t), 1e-12f);
    }
    __syncthreads();
    if (o < 64) out_mu[(size_t)kb*EE + o] = h * sinv;
    else        out_lv[(size_t)kb*EE + (o-64)] = -h;
}

// ---------------- decoder ----------------
__global__ void __launch_bounds__(256) decoder_k(
        const float* __restrict__ items, const float* __restrict__ cates,
        const float* __restrict__ mu, float* __restrict__ out, int N)
{
    __shared__ float itemsT[64][68];
    __shared__ float mu_s[16][64][4];    // [b][e][k]
    __shared__ float cs[64][4];
    int tid = threadIdx.x;
    int tx = tid & 15, ty = tid >> 4;
    int n0 = blockIdx.x * 64;
    int bt = blockIdx.y * 16;
    #pragma unroll
    for (int i = 0; i < 16; i++) {
        int idx = tid + i*256;
        int n = idx >> 6, e = idx & 63;
        itemsT[e][n] = items[(size_t)(n0+n)*EE + e];
    }
    #pragma unroll
    for (int i = 0; i < 16; i++) {
        int idx = tid + i*256;
        int kb = idx >> 6, e = idx & 63;
        int k = kb >> 4, b = kb & 15;
        mu_s[b][e][k] = mu[(size_t)(k*BB + bt + b)*EE + e];
    }
    {
        int n = tid >> 2, kk = tid & 3;
        cs[n][kk] = cates[(size_t)(n0+n)*KP + kk];
    }
    __syncthreads();

    float acc[4][KP];
    #pragma unroll
    for (int i = 0; i < 4; i++)
        #pragma unroll
        for (int k = 0; k < KP; k++) acc[i][k] = 0.f;

    #pragma unroll 4
    for (int e = 0; e < 64; e++) {
        float4 a = *(const float4*)&itemsT[e][tx*4];
        float4 mm = *(const float4*)&mu_s[ty][e][0];
        float aw[4] = {a.x, a.y, a.z, a.w};
        #pragma unroll
        for (int i = 0; i < 4; i++) {
            acc[i][0] += aw[i]*mm.x; acc[i][1] += aw[i]*mm.y;
            acc[i][2] += aw[i]*mm.z; acc[i][3] += aw[i]*mm.w;
        }
    }
    int b = bt + ty;
    #pragma unroll
    for (int i = 0; i < 4; i++) {
        int nl = tx*4 + i;
        float4 c = *(const float4*)&cs[nl][0];
        float p = __expf(acc[i][0])*c.x + __expf(acc[i][1])*c.y
                + __expf(acc[i][2])*c.z + __expf(acc[i][3])*c.w;
        out[(size_t)b*N + n0 + nl] = __logf(p);
    }
}

// ---------------- launch ----------------
extern "C" void kernel_launch(void* const* d_in, const int* in_sizes, int n_in,
                              void* d_out, int out_size)
{
    const float* x_cf    = (const float*)d_in[0];
    const float* x_tx    = (const float*)d_in[1];
    const float* adj     = (const float*)d_in[2];
    const float* cf_emb  = (const float*)d_in[3];
    const float* cf_prot = (const float*)d_in[4];
    const float* cf_W    = (const float*)d_in[5];
    const float* cf_b    = (const float*)d_in[6];
    const float* tx_emb  = (const float*)d_in[7];
    const float* tx_prot = (const float*)d_in[8];
    const float* tx_W    = (const float*)d_in[9];
    const float* tx_b    = (const float*)d_in[10];
    float* out = (float*)d_out;

    float *p_protos_cf, *p_protos_tx, *p_items_cf, *p_items_tx;
    float *p_cates_cf, *p_cates_tx, *p_ctT_cf, *p_ctT_tx, *p_rnp_cf, *p_rnp_tx;
    float *p_P1, *p_M, *p_big, *p_part_cf, *p_part_tx;
    cudaGetSymbolAddress((void**)&p_protos_cf, g_protos_cf);
    cudaGetSymbolAddress((void**)&p_protos_tx, g_protos_tx);
    cudaGetSymbolAddress((void**)&p_items_cf,  g_items_cf);
    cudaGetSymbolAddress((void**)&p_items_tx,  g_items_tx);
    cudaGetSymbolAddress((void**)&p_cates_cf,  g_cates_cf);
    cudaGetSymbolAddress((void**)&p_cates_tx,  g_cates_tx);
    cudaGetSymbolAddress((void**)&p_ctT_cf,    g_ctT_cf);
    cudaGetSymbolAddress((void**)&p_ctT_tx,    g_ctT_tx);
    cudaGetSymbolAddress((void**)&p_rnp_cf,    g_rnp_cf);
    cudaGetSymbolAddress((void**)&p_rnp_tx,    g_rnp_tx);
    cudaGetSymbolAddress((void**)&p_P1,        g_P1);
    cudaGetSymbolAddress((void**)&p_M,         g_M);
    cudaGetSymbolAddress((void**)&p_big,       g_bigpart);
    cudaGetSymbolAddress((void**)&p_part_cf,   g_part_cf);
    cudaGetSymbolAddress((void**)&p_part_tx,   g_part_tx);

    // streams/events created once, outside capture (first call is the
    // uncaptured correctness run)
    static cudaStream_t s_tx = nullptr, s_pre = nullptr;
    static cudaEvent_t ev_fork = nullptr, ev_tx = nullptr, ev_pre = nullptr;
    if (!s_tx) {
        cudaStreamCreateWithFlags(&s_tx,  cudaStreamNonBlocking);
        cudaStreamCreateWithFlags(&s_pre, cudaStreamNonBlocking);
        cudaEventCreateWithFlags(&ev_fork, cudaEventDisableTiming);
        cudaEventCreateWithFlags(&ev_tx,   cudaEventDisableTiming);
        cudaEventCreateWithFlags(&ev_pre,  cudaEventDisableTiming);
    }

    // ---- stem: prototypes (both branches), then fork ----
    proto_norm_k<<<1, 256>>>(cf_prot, tx_prot);
    cudaEventRecord(ev_fork, 0);
    cudaStreamWaitEvent(s_tx,  ev_fork, 0);
    cudaStreamWaitEvent(s_pre, ev_fork, 0);

    // ---- text branch (independent of adj chain) on s_tx ----
    items_cates_k<<<NW/8, 256, 0, s_tx>>>(tx_emb, p_protos_tx, p_items_tx, p_cates_tx, p_ctT_tx, NW);
    rnormp_k<<<dim3(BB, 8), 256, 0, s_tx>>>(x_tx, p_cates_tx, p_rnp_tx, NW);
    mma_gemm_k<<<dim3(4, 1, HSPLIT), 256, 0, s_tx>>>(x_tx, p_ctT_tx, tx_W, p_part_tx,
                                                     512, NW, NW/HSPLIT, 1, 1);
    hfinal_k<<<KP*BB, 128, 0, s_tx>>>(p_part_tx, HSPLIT, p_rnp_tx, tx_b,
                                      out + OUT_TXMU, out + OUT_TXLV);
    decoder_k<<<dim3(NW/64, BB/16), 256, 0, s_tx>>>(p_items_tx, p_cates_tx,
                                                    out + OUT_TXMU, out + OUT_TEXT, NW);
    cudaEventRecord(ev_tx, s_tx);

    // ---- cf prep (independent of P1/P2) on s_pre ----
    items_cates_k<<<NI/8, 256, 0, s_pre>>>(cf_emb, p_protos_cf, p_items_cf, p_cates_cf, p_ctT_cf, NI);
    rnormp_k<<<dim3(BB, 8), 256, 0, s_pre>>>(x_cf, p_cates_cf, p_rnp_cf, NI);
    cudaEventRecord(ev_pre, s_pre);

    // ---- adjacency chain on the capture stream ----
    mma_gemm_k<<<dim3(NI/128, 1, 8), 256>>>(adj, nullptr, cf_W, p_big, NI, NI, NI/8, 0, 1);
    reduce8_k<<<(NI*TWOE/4 + 255)/256, 256>>>(p_big, p_P1, NI*TWOE/4, NI*TWOE/4);
    mma_gemm_k<<<dim3(NI/128, 1, 8), 256>>>(adj, nullptr, p_P1, p_big, NI, NI, NI/8, 0, 0);
    reduceM_k<<<NI*TWOE/256, 256>>>(p_big, cf_W, p_M);

    // hpart_cf needs ctT_cf from s_pre
    cudaStreamWaitEvent(0, ev_pre, 0);
    mma_gemm_k<<<dim3(4, 1, HSPLIT), 256>>>(x_cf, p_ctT_cf, p_M, p_part_cf,
                                            512, NI, NI/HSPLIT, 1, 0);
    hfinal_k<<<KP*BB, 128>>>(p_part_cf, HSPLIT, p_rnp_cf, cf_b,
                             out + OUT_CFMU, out + OUT_CFLV);
    decoder_k<<<dim3(NI/64, BB/16), 256>>>(p_items_cf, p_cates_cf,
                                           out + OUT_CFMU, out + OUT_RATING, NI);

    // ---- join text branch ----
    cudaStreamWaitEvent(0, ev_tx, 0);
}

// round 5
// speedup vs baseline: 7.4116x; 1.1773x over previous
#include <cuda_runtime.h>
#include <math.h>
#include <stdint.h>

// ---------------- problem constants ----------------
#define BB    128
#define NI    8192
#define NW    16384
#define EE    64
#define KP    4
#define TWOE  128

#define OUT_RATING  0
#define OUT_TEXT    (128*8192)
#define OUT_CFMU    (OUT_TEXT + 128*16384)
#define OUT_CFLV    (OUT_CFMU + 4*128*64)
#define OUT_TXMU    (OUT_CFLV + 4*128*64)
#define OUT_TXLV    (OUT_TXMU + 4*128*64)

#define HSPLIT 64

// GEMM tile config
#define BLKK   32
#define S_LD   36                       // padded row stride (words): 144B, odd*16 banks
#define BUF_B  (128*S_LD*4)             // 18432 bytes per buffer
#define SMEM_GEMM (4*BUF_B)             // As[2] + Bs[2] = 73728

// ---------------- scratch ----------------
__device__ float g_protos_cf[KP*EE];
__device__ float g_protos_tx[KP*EE];
__device__ float g_items_cf[NI*EE];
__device__ float g_items_tx[NW*EE];
__device__ float g_cates_cf[NI*KP];
__device__ float g_cates_tx[NW*KP];
__device__ float g_ctT_cf[KP*NI];
__device__ float g_ctT_tx[KP*NW];
__device__ float g_rnp_cf[KP*BB*8];
__device__ float g_rnp_tx[KP*BB*8];
__device__ float g_P1T[TWOE*NI];        // P1 transposed [o][n]
__device__ float g_MT [TWOE*NI];        // M transposed [o][n]
__device__ float g_bigpart[8*NI*TWOE];
__device__ float g_part_cf[HSPLIT*512*TWOE];
__device__ float g_part_tx[HSPLIT*512*TWOE];

// ---------------- k0: normalize prototypes ----------------
__global__ void proto_norm_k(const float* __restrict__ cfp, const float* __restrict__ txp) {
    int tid = threadIdx.x;
    int w = tid >> 5, lane = tid & 31;
    const float* src = (w < 4) ? cfp : txp;
    float* dst = (w < 4) ? g_protos_cf : g_protos_tx;
    int row = w & 3;
    float v0 = src[row*EE + lane];
    float v1 = src[row*EE + 32 + lane];
    float s = v0*v0 + v1*v1;
    #pragma unroll
    for (int off = 16; off; off >>= 1) s += __shfl_xor_sync(0xffffffffu, s, off);
    float inv = 1.0f / fmaxf(sqrtf(s), 1e-12f);
    dst[row*EE + lane]      = v0 * inv;
    dst[row*EE + 32 + lane] = v1 * inv;
}

// ---------------- k1: item norm + cates softmax (+ transposed) ----------------
__global__ void __launch_bounds__(256) items_cates_k(
        const float* __restrict__ emb, const float* __restrict__ protos_g,
        float* __restrict__ items_out, float* __restrict__ cates_out,
        float* __restrict__ catesT_out, int N)
{
    __shared__ float ps[KP*EE];
    int tid = threadIdx.x;
    ps[tid] = protos_g[tid];
    __syncthreads();
    int w = tid >> 5, lane = tid & 31;
    int n = blockIdx.x * 8 + w;
    if (n >= N) return;
    float v0 = emb[n*EE + lane];
    float v1 = emb[n*EE + 32 + lane];
    float s = v0*v0 + v1*v1;
    #pragma unroll
    for (int off = 16; off; off >>= 1) s += __shfl_xor_sync(0xffffffffu, s, off);
    float inv = 1.0f / fmaxf(sqrtf(s), 1e-12f);
    float h0 = v0 * inv, h1 = v1 * inv;
    items_out[n*EE + lane]      = h0;
    items_out[n*EE + 32 + lane] = h1;
    float d[KP];
    #pragma unroll
    for (int k = 0; k < KP; k++) {
        float dk = h0 * ps[k*EE + lane] + h1 * ps[k*EE + 32 + lane];
        #pragma unroll
        for (int off = 16; off; off >>= 1) dk += __shfl_xor_sync(0xffffffffu, dk, off);
        d[k] = dk;
    }
    if (lane == 0) {
        float m = fmaxf(fmaxf(d[0], d[1]), fmaxf(d[2], d[3]));
        float e0 = __expf(d[0]-m), e1 = __expf(d[1]-m), e2 = __expf(d[2]-m), e3 = __expf(d[3]-m);
        float is = 1.0f / (e0+e1+e2+e3);
        float c0 = e0*is, c1 = e1*is, c2 = e2*is, c3 = e3*is;
        *(float4*)&cates_out[n*KP] = make_float4(c0, c1, c2, c3);
        catesT_out[0*N + n] = c0;
        catesT_out[1*N + n] = c1;
        catesT_out[2*N + n] = c2;
        catesT_out[3*N + n] = c3;
    }
}

// ---------------- k2: rnorm partials over 8 n-chunks ----------------
__global__ void __launch_bounds__(256) rnormp_k(
        const float* __restrict__ x, const float* __restrict__ cates,
        float* __restrict__ rnp, int N)
{
    __shared__ float red[8][KP];
    int b = blockIdx.x, chunk = blockIdx.y, tid = threadIdx.x;
    int n0 = chunk * (N >> 3), n1 = n0 + (N >> 3);
    float s0=0.f, s1=0.f, s2=0.f, s3=0.f;
    const float* xr = x + (size_t)b * N;
    for (int n = n0 + tid; n < n1; n += 256) {
        float xv = xr[n];
        float4 c = *(const float4*)&cates[n*KP];
        float t0 = xv*c.x, t1 = xv*c.y, t2 = xv*c.z, t3 = xv*c.w;
        s0 += t0*t0; s1 += t1*t1; s2 += t2*t2; s3 += t3*t3;
    }
    #pragma unroll
    for (int off = 16; off; off >>= 1) {
        s0 += __shfl_xor_sync(0xffffffffu, s0, off);
        s1 += __shfl_xor_sync(0xffffffffu, s1, off);
        s2 += __shfl_xor_sync(0xffffffffu, s2, off);
        s3 += __shfl_xor_sync(0xffffffffu, s3, off);
    }
    int w = tid >> 5;
    if ((tid & 31) == 0) { red[w][0]=s0; red[w][1]=s1; red[w][2]=s2; red[w][3]=s3; }
    __syncthreads();
    if (tid < KP) {
        float t = 0.f;
        #pragma unroll
        for (int i = 0; i < 8; i++) t += red[i][tid];
        rnp[(tid*BB + b)*8 + chunk] = t;
    }
}

// ---------------- TF32 / mma / ldmatrix helpers ----------------
__device__ __forceinline__ uint32_t f2tf(float f) {
    uint32_t r;
    asm("cvt.rna.tf32.f32 %0, %1;" : "=r"(r) : "f"(f));
    return r;
}
__device__ __forceinline__ void mma_tf32(float c[4], const uint32_t a[4],
                                         uint32_t b0, uint32_t b1) {
    asm volatile(
        "mma.sync.aligned.m16n8k8.row.col.f32.tf32.tf32.f32 "
        "{%0,%1,%2,%3}, {%4,%5,%6,%7}, {%8,%9}, {%0,%1,%2,%3};"
        : "+f"(c[0]), "+f"(c[1]), "+f"(c[2]), "+f"(c[3])
        : "r"(a[0]), "r"(a[1]), "r"(a[2]), "r"(a[3]), "r"(b0), "r"(b1));
}
__device__ __forceinline__ void ldsm4(uint32_t& r0, uint32_t& r1,
                                      uint32_t& r2, uint32_t& r3, uint32_t addr) {
    asm volatile("ldmatrix.sync.aligned.m8n8.x4.shared.b16 {%0,%1,%2,%3}, [%4];"
                 : "=r"(r0), "=r"(r1), "=r"(r2), "=r"(r3) : "r"(addr));
}

// ---------------- TF32 MMA GEMM, 128x128 tile, BLKK=32, ldmatrix fragments ----
// A: amode 0: row-major [m][Ktot] (m global = bx*128+m); amode 1: Y[m][n]=x[m][n]*ctT[bx][n]
// B: ALWAYS rows [o][Ktot] (o = 0..127)
// out: part[(bz*Mrows + row)*128 + o]
__global__ void __launch_bounds__(256, 2) mma_gemm_k(
        const float* __restrict__ A, const float* __restrict__ ctT,
        const float* __restrict__ B, float* __restrict__ part,
        int Mrows, int Ktot, int Ksplit, int amode)
{
    extern __shared__ uint32_t smem[];
    uint32_t* Asm = smem;                        // [2][128][S_LD]
    uint32_t* Bsm = smem + 2*128*S_LD;           // [2][128][S_LD]
    int tid = threadIdx.x;
    int lane = tid & 31, w = tid >> 5;
    int wm = w & 3, wn = w >> 2;
    int lr = lane >> 2, lc = lane & 3;
    int m0 = blockIdx.x * 128;
    int kc0 = blockIdx.z * Ksplit;
    int niter = Ksplit / BLKK;
    const float* ctb = amode ? (ctT + (size_t)blockIdx.x * Ktot) : (const float*)0;

    uint32_t as_base = (uint32_t)__cvta_generic_to_shared(Asm);
    uint32_t bs_base = (uint32_t)__cvta_generic_to_shared(Bsm);
    int sel = lane >> 3, lr8 = lane & 7;
    // ldmatrix per-lane base offsets (bytes)
    uint32_t a_off = ((wm*32 + (sel&1)*8 + lr8)*S_LD + (sel>>1)*4) * 4;
    uint32_t b_off = ((wn*64 + (sel>>1)*8 + lr8)*S_LD + (sel&1)*4) * 4;

    float acc[2][8][4];
    #pragma unroll
    for (int mt = 0; mt < 2; mt++)
        #pragma unroll
        for (int nt = 0; nt < 8; nt++)
            #pragma unroll
            for (int i = 0; i < 4; i++) acc[mt][nt][i] = 0.f;

    float4 ra[4], rb[4];
    int am = tid >> 3, akq = (tid & 7) * 4;      // A loader coords (m, k-quad)
    int bo = tid >> 1, bk0 = (tid & 1) * 16;     // B loader coords

    auto ldA = [&](int kc) {
        #pragma unroll
        for (int i = 0; i < 4; i++) {
            int m = am, kq = akq;  (void)m;
            int mm = (tid + i*256) >> 3;
            int kk = ((tid + i*256) & 7) * 4;
            if (amode == 0) {
                ra[i] = *(const float4*)(A + (size_t)(m0 + mm) * Ktot + kc + kk);
            } else {
                float4 v = *(const float4*)(A + (size_t)mm * Ktot + kc + kk);
                float4 c = *(const float4*)(ctb + kc + kk);
                v.x *= c.x; v.y *= c.y; v.z *= c.z; v.w *= c.w;
                ra[i] = v;
            }
        }
    };
    auto stA = [&](int buf) {
        uint32_t* base = Asm + buf*128*S_LD;
        #pragma unroll
        for (int i = 0; i < 4; i++) {
            int mm = (tid + i*256) >> 3;
            int kk = ((tid + i*256) & 7) * 4;
            uint4 u;
            u.x = f2tf(ra[i].x); u.y = f2tf(ra[i].y);
            u.z = f2tf(ra[i].z); u.w = f2tf(ra[i].w);
            *(uint4*)(base + mm*S_LD + kk) = u;
        }
    };
    auto ldB = [&](int kc) {
        #pragma unroll
        for (int i = 0; i < 4; i++)
            rb[i] = *(const float4*)(B + (size_t)bo * Ktot + kc + bk0 + i*4);
    };
    auto stB = [&](int buf) {
        uint32_t* base = Bsm + buf*128*S_LD + bo*S_LD + bk0;
        #pragma unroll
        for (int i = 0; i < 4; i++) {
            uint4 u;
            u.x = f2tf(rb[i].x); u.y = f2tf(rb[i].y);
            u.z = f2tf(rb[i].z); u.w = f2tf(rb[i].w);
            *(uint4*)(base + i*4) = u;
        }
    };
    auto compute = [&](int buf) {
        uint32_t abase = as_base + buf*BUF_B + a_off;
        uint32_t bbase = bs_base + buf*BUF_B + b_off;
        #pragma unroll
        for (int ks = 0; ks < 4; ks++) {
            int k0b = ks * 8 * 4;                // k0 in bytes
            uint32_t afr[2][4];
            #pragma unroll
            for (int mt = 0; mt < 2; mt++)
                ldsm4(afr[mt][0], afr[mt][1], afr[mt][2], afr[mt][3],
                      abase + mt*(16*S_LD*4) + k0b);
            #pragma unroll
            for (int np = 0; np < 4; np++) {
                uint32_t b0, b1, b2, b3;
                ldsm4(b0, b1, b2, b3, bbase + np*(16*S_LD*4) + k0b);
                mma_tf32(acc[0][2*np  ], afr[0], b0, b1);
                mma_tf32(acc[1][2*np  ], afr[1], b0, b1);
                mma_tf32(acc[0][2*np+1], afr[0], b2, b3);
                mma_tf32(acc[1][2*np+1], afr[1], b2, b3);
            }
        }
    };

    ldA(kc0); ldB(kc0); stA(0); stB(0);
    __syncthreads();
    for (int it = 0; it < niter; it++) {
        int cur = it & 1;
        if (it + 1 < niter) { ldA(kc0 + (it+1)*BLKK); ldB(kc0 + (it+1)*BLKK); }
        compute(cur);
        if (it + 1 < niter) { stA(1-cur); stB(1-cur); }
        __syncthreads();
    }

    #pragma unroll
    for (int mt = 0; mt < 2; mt++)
        #pragma unroll
        for (int nt = 0; nt < 8; nt++) {
            int row = m0 + wm*32 + mt*16 + lr;
            int col = wn*64 + nt*8 + lc*2;
            float* p = part + ((size_t)blockIdx.z * Mrows + row) * TWOE + col;
            *(float2*)p             = make_float2(acc[mt][nt][0], acc[mt][nt][1]);
            *(float2*)(p + 8*TWOE)  = make_float2(acc[mt][nt][2], acc[mt][nt][3]);
        }
}

// ---------------- reduce split-K partials + transpose (tiled) ----------------
// in: part[z][n][o] (z stride NI*TWOE); out: outT[o][n]  (optionally 0.5*(v + W[o][n]))
__global__ void __launch_bounds__(256) reduceT_k(
        const float* __restrict__ part, const float* __restrict__ W,
        float* __restrict__ outT, int combine)
{
    __shared__ float t[64][65];
    int n0 = blockIdx.x * 64, o0 = blockIdx.y * 64;
    int c0 = threadIdx.x & 63, r4 = threadIdx.x >> 6;
    #pragma unroll
    for (int p = 0; p < 16; p++) {
        int nl = p*4 + r4;
        float s = 0.f;
        #pragma unroll
        for (int z = 0; z < 8; z++)
            s += part[((size_t)z*NI + n0 + nl)*TWOE + o0 + c0];
        t[nl][c0] = s;
    }
    __syncthreads();
    #pragma unroll
    for (int p = 0; p < 16; p++) {
        int ol = p*4 + r4;
        float v = t[c0][ol];
        if (combine) v = 0.5f*(v + W[(size_t)(o0+ol)*NI + n0 + c0]);
        outT[(size_t)(o0+ol)*NI + n0 + c0] = v;
    }
}

// ---------------- finalize h -> mu / logvar ----------------
__global__ void __launch_bounds__(128) hfinal_k(
        const float* __restrict__ part, int nchunks,
        const float* __restrict__ rnp, const float* __restrict__ bias,
        float* __restrict__ out_mu, float* __restrict__ out_lv)
{
    __shared__ float sq[64];
    __shared__ float sinv, s_rn;
    int kb = blockIdx.x, o = threadIdx.x;
    if (o == 0) {
        float t = 0.f;
        #pragma unroll
        for (int c = 0; c < 8; c++) t += rnp[kb*8 + c];
        s_rn = 1.0f / fmaxf(sqrtf(t), 1e-12f);
    }
    float s = 0.f;
    for (int c = 0; c < nchunks; c++) s += part[(size_t)c*512*TWOE + (size_t)kb*TWOE + o];
    __syncthreads();
    float h = s * s_rn + bias[o];
    if (o < 64) sq[o] = h*h;
    __syncthreads();
    if (o == 0) {
        float t = 0.f;
        #pragma unroll
        for (int i = 0; i < 64; i++) t += sq[i];
        sinv = 1.0f / fmaxf(sqrtf(t), 1e-12f);
    }
    __syncthreads();
    if (o < 64) out_mu[(size_t)kb*EE + o] = h * sinv;
    else        out_lv[(size_t)kb*EE + (o-64)] = -h;
}

// ---------------- decoder ----------------
__global__ void __launch_bounds__(256) decoder_k(
        const float* __restrict__ items, const float* __restrict__ cates,
        const float* __restrict__ mu, float* __restrict__ out, int N)
{
    __shared__ float itemsT[64][68];
    __shared__ float mu_s[16][64][4];
    __shared__ float cs[64][4];
    int tid = threadIdx.x;
    int tx = tid & 15, ty = tid >> 4;
    int n0 = blockIdx.x * 64;
    int bt = blockIdx.y * 16;
    #pragma unroll
    for (int i = 0; i < 16; i++) {
        int idx = tid + i*256;
        int n = idx >> 6, e = idx & 63;
        itemsT[e][n] = items[(size_t)(n0+n)*EE + e];
    }
    #pragma unroll
    for (int i = 0; i < 16; i++) {
        int idx = tid + i*256;
        int kb = idx >> 6, e = idx & 63;
        int k = kb >> 4, b = kb & 15;
        mu_s[b][e][k] = mu[(size_t)(k*BB + bt + b)*EE + e];
    }
    {
        int n = tid >> 2, kk = tid & 3;
        cs[n][kk] = cates[(size_t)(n0+n)*KP + kk];
    }
    __syncthreads();

    float acc[4][KP];
    #pragma unroll
    for (int i = 0; i < 4; i++)
        #pragma unroll
        for (int k = 0; k < KP; k++) acc[i][k] = 0.f;

    #pragma unroll 4
    for (int e = 0; e < 64; e++) {
        float4 a = *(const float4*)&itemsT[e][tx*4];
        float4 mm = *(const float4*)&mu_s[ty][e][0];
        float aw[4] = {a.x, a.y, a.z, a.w};
        #pragma unroll
        for (int i = 0; i < 4; i++) {
            acc[i][0] += aw[i]*mm.x; acc[i][1] += aw[i]*mm.y;
            acc[i][2] += aw[i]*mm.z; acc[i][3] += aw[i]*mm.w;
        }
    }
    int b = bt + ty;
    #pragma unroll
    for (int i = 0; i < 4; i++) {
        int nl = tx*4 + i;
        float4 c = *(const float4*)&cs[nl][0];
        float p = __expf(acc[i][0])*c.x + __expf(acc[i][1])*c.y
                + __expf(acc[i][2])*c.z + __expf(acc[i][3])*c.w;
        out[(size_t)b*N + n0 + nl] = __logf(p);
    }
}

// ---------------- launch ----------------
extern "C" void kernel_launch(void* const* d_in, const int* in_sizes, int n_in,
                              void* d_out, int out_size)
{
    const float* x_cf    = (const float*)d_in[0];
    const float* x_tx    = (const float*)d_in[1];
    const float* adj     = (const float*)d_in[2];
    const float* cf_emb  = (const float*)d_in[3];
    const float* cf_prot = (const float*)d_in[4];
    const float* cf_W    = (const float*)d_in[5];
    const float* cf_b    = (const float*)d_in[6];
    const float* tx_emb  = (const float*)d_in[7];
    const float* tx_prot = (const float*)d_in[8];
    const float* tx_W    = (const float*)d_in[9];
    const float* tx_b    = (const float*)d_in[10];
    float* out = (float*)d_out;

    float *p_protos_cf, *p_protos_tx, *p_items_cf, *p_items_tx;
    float *p_cates_cf, *p_cates_tx, *p_ctT_cf, *p_ctT_tx, *p_rnp_cf, *p_rnp_tx;
    float *p_P1T, *p_MT, *p_big, *p_part_cf, *p_part_tx;
    cudaGetSymbolAddress((void**)&p_protos_cf, g_protos_cf);
    cudaGetSymbolAddress((void**)&p_protos_tx, g_protos_tx);
    cudaGetSymbolAddress((void**)&p_items_cf,  g_items_cf);
    cudaGetSymbolAddress((void**)&p_items_tx,  g_items_tx);
    cudaGetSymbolAddress((void**)&p_cates_cf,  g_cates_cf);
    cudaGetSymbolAddress((void**)&p_cates_tx,  g_cates_tx);
    cudaGetSymbolAddress((void**)&p_ctT_cf,    g_ctT_cf);
    cudaGetSymbolAddress((void**)&p_ctT_tx,    g_ctT_tx);
    cudaGetSymbolAddress((void**)&p_rnp_cf,    g_rnp_cf);
    cudaGetSymbolAddress((void**)&p_rnp_tx,    g_rnp_tx);
    cudaGetSymbolAddress((void**)&p_P1T,       g_P1T);
    cudaGetSymbolAddress((void**)&p_MT,        g_MT);
    cudaGetSymbolAddress((void**)&p_big,       g_bigpart);
    cudaGetSymbolAddress((void**)&p_part_cf,   g_part_cf);
    cudaGetSymbolAddress((void**)&p_part_tx,   g_part_tx);

    static cudaStream_t s_tx = nullptr, s_pre = nullptr;
    static cudaEvent_t ev_fork = nullptr, ev_tx = nullptr, ev_pre = nullptr;
    if (!s_tx) {
        cudaStreamCreateWithFlags(&s_tx,  cudaStreamNonBlocking);
        cudaStreamCreateWithFlags(&s_pre, cudaStreamNonBlocking);
        cudaEventCreateWithFlags(&ev_fork, cudaEventDisableTiming);
        cudaEventCreateWithFlags(&ev_tx,   cudaEventDisableTiming);
        cudaEventCreateWithFlags(&ev_pre,  cudaEventDisableTiming);
        cudaFuncSetAttribute(mma_gemm_k,
            cudaFuncAttributeMaxDynamicSharedMemorySize, SMEM_GEMM);
    }

    // ---- stem ----
    proto_norm_k<<<1, 256>>>(cf_prot, tx_prot);
    cudaEventRecord(ev_fork, 0);
    cudaStreamWaitEvent(s_tx,  ev_fork, 0);
    cudaStreamWaitEvent(s_pre, ev_fork, 0);

    // ---- text branch on s_tx ----
    items_cates_k<<<NW/8, 256, 0, s_tx>>>(tx_emb, p_protos_tx, p_items_tx, p_cates_tx, p_ctT_tx, NW);
    rnormp_k<<<dim3(BB, 8), 256, 0, s_tx>>>(x_tx, p_cates_tx, p_rnp_tx, NW);
    mma_gemm_k<<<dim3(4, 1, HSPLIT), 256, SMEM_GEMM, s_tx>>>(
        x_tx, p_ctT_tx, tx_W, p_part_tx, 512, NW, NW/HSPLIT, 1);
    hfinal_k<<<KP*BB, 128, 0, s_tx>>>(p_part_tx, HSPLIT, p_rnp_tx, tx_b,
                                      out + OUT_TXMU, out + OUT_TXLV);
    decoder_k<<<dim3(NW/64, BB/16), 256, 0, s_tx>>>(p_items_tx, p_cates_tx,
                                                    out + OUT_TXMU, out + OUT_TEXT, NW);
    cudaEventRecord(ev_tx, s_tx);

    // ---- cf prep on s_pre ----
    items_cates_k<<<NI/8, 256, 0, s_pre>>>(cf_emb, p_protos_cf, p_items_cf, p_cates_cf, p_ctT_cf, NI);
    rnormp_k<<<dim3(BB, 8), 256, 0, s_pre>>>(x_cf, p_cates_cf, p_rnp_cf, NI);
    cudaEventRecord(ev_pre, s_pre);

    // ---- adjacency chain ----
    // P1 = adj @ cf_W^T  -> P1T [o][n]
    mma_gemm_k<<<dim3(NI/128, 1, 8), 256, SMEM_GEMM>>>(
        adj, nullptr, cf_W, p_big, NI, NI, NI/8, 0);
    reduceT_k<<<dim3(NI/64, 2), 256>>>(p_big, nullptr, p_P1T, 0);
    // P2 = adj @ P1  (B rows = P1T[o][n]) -> MT = 0.5*(P2T + W)
    mma_gemm_k<<<dim3(NI/128, 1, 8), 256, SMEM_GEMM>>>(
        adj, nullptr, p_P1T, p_big, NI, NI, NI/8, 0);
    reduceT_k<<<dim3(NI/64, 2), 256>>>(p_big, cf_W, p_MT, 1);

    // hpart_cf (B rows = MT[o][n])
    cudaStreamWaitEvent(0, ev_pre, 0);
    mma_gemm_k<<<dim3(4, 1, HSPLIT), 256, SMEM_GEMM>>>(
        x_cf, p_ctT_cf, p_MT, p_part_cf, 512, NI, NI/HSPLIT, 1);
    hfinal_k<<<KP*BB, 128>>>(p_part_cf, HSPLIT, p_rnp_cf, cf_b,
                             out + OUT_CFMU, out + OUT_CFLV);
    decoder_k<<<dim3(NI/64, BB/16), 256>>>(p_items_cf, p_cates_cf,
                                           out + OUT_CFMU, out + OUT_RATING, NI);

    cudaStreamWaitEvent(0, ev_tx, 0);
}